// round 12
// baseline (speedup 1.0000x reference)
#include <cuda_runtime.h>
#include <cstdint>

#define Bsz 256
#define Tt  2048
#define Dd  57
#define DP  60            // padded Dd (float4 friendly)
#define Hh  16
#define G4  64
#define GR  64            // rows per gemm0 block
#define IV  8             // steps per interval (ring-safe)
#define NIV (Tt / IV)     // 256 intervals
#define XD  32            // xg ring depth (steps, pow2)
#define PD  16            // projection ring depth (steps, pow2)

typedef unsigned long long ull;

// Scratch (device-global: no allocation allowed in kernel_launch)
// g_xg layout per (b,t): 16 chunks of 16B; chunk u = (row u, row u+32,
// row u+16, row u+48) = (i,g,f,o) of unit u, biases included.
__device__ float g_xg[(size_t)Bsz * Tt * G4];
__device__ float g_h [(size_t)Bsz * Tt * Hh];   // masked layer-2 hidden states
__device__ float g_psum[Bsz * Hh];              // per-batch partial BN sums
__device__ float g_psq [Bsz * Hh];
__device__ float g_scale[Hh], g_shift[Hh];

// HW tanh (MUFU.TANH)
__device__ __forceinline__ float tanha(float x) {
    float y; asm("tanh.approx.f32 %0, %1;" : "=f"(y) : "f"(x)); return y;
}
__device__ __forceinline__ float siga(float x) {
    return fmaf(0.5f, tanha(0.5f * x), 0.5f);
}

// --- packed f32x2 helpers ---
__device__ __forceinline__ ull pk2(float a, float b) {
    ull r; asm("mov.b64 %0, {%1, %2};" : "=l"(r) : "f"(a), "f"(b)); return r;
}
__device__ __forceinline__ void upk2(ull v, float& a, float& b) {
    asm("mov.b64 {%0, %1}, %2;" : "=f"(a), "=f"(b) : "l"(v));
}
__device__ __forceinline__ ull fma2(ull a, ull b, ull c) {
    ull d; asm("fma.rn.f32x2 %0, %1, %2, %3;" : "=l"(d) : "l"(a), "l"(b), "l"(c));
    return d;
}
__device__ __forceinline__ ull add2(ull a, ull b) {
    ull d; asm("add.rn.f32x2 %0, %1, %2;" : "=l"(d) : "l"(a), "l"(b));
    return d;
}

__device__ __forceinline__ void cp_async16(uint32_t smem_addr, const void* gptr) {
    asm volatile("cp.async.cg.shared.global [%0], [%1], 16;"
                 :: "r"(smem_addr), "l"(gptr) : "memory");
}
__device__ __forceinline__ void cp_commit() {
    asm volatile("cp.async.commit_group;" ::: "memory");
}
template <int N>
__device__ __forceinline__ void cp_wait() {
    asm volatile("cp.async.wait_group %0;" :: "n"(N) : "memory");
}

// No-op kernel: shifts ncu's capture slot (-s 5) onto lstm_pipe.
__global__ void nop_kernel() {}

// ---------------------------------------------------------------------------
// Kernel 1: xg0 = x @ W_ih0^T + b.  64 rows/block, interleaved output.
// ---------------------------------------------------------------------------
__global__ __launch_bounds__(512) void gemm0_kernel(
    const float* __restrict__ x,
    const float* __restrict__ W,
    const float* __restrict__ bi,
    const float* __restrict__ bh) {
    __shared__ float Ws[G4 * DP];
    __shared__ float bs[G4];
    __shared__ float xs[GR * DP];
    int tid = threadIdx.x;

    for (int i = tid; i < G4 * DP; i += 512) Ws[i] = 0.f;
    for (int i = tid; i < GR * DP; i += 512) xs[i] = 0.f;
    __syncthreads();
    for (int i = tid; i < G4 * Dd; i += 512)
        Ws[(i / Dd) * DP + (i % Dd)] = W[i];
    if (tid < G4) bs[tid] = bi[tid] + bh[tid];
    size_t r0 = (size_t)blockIdx.x * GR;
    for (int i = tid; i < GR * Dd; i += 512)
        xs[(i / Dd) * DP + (i % Dd)] = x[r0 * Dd + i];
    __syncthreads();

    int g  = tid & 63;
    int y0 = tid >> 6;            // rows y0, y0+8, ..., y0+56
    float acc[8];
    #pragma unroll
    for (int m = 0; m < 8; m++) acc[m] = bs[g];

    const float4* Ws4 = (const float4*)Ws;
    const float4* xs4 = (const float4*)xs;
    #pragma unroll
    for (int d4 = 0; d4 < DP / 4; d4++) {
        float4 wv = Ws4[g * (DP / 4) + d4];
        #pragma unroll
        for (int m = 0; m < 8; m++) {
            float4 xv = xs4[(y0 + 8 * m) * (DP / 4) + d4];
            acc[m] += xv.x * wv.x + xv.y * wv.y + xv.z * wv.z + xv.w * wv.w;
        }
    }

    int pos = (g & 15) * 4 + ((g >> 4) & 1) * 2 + (g >> 5);
    #pragma unroll
    for (int m = 0; m < 8; m++)
        g_xg[(r0 + y0 + 8 * m) * G4 + pos] = acc[m];
}

// ---------------------------------------------------------------------------
// Kernel 2: layer-pipelined LSTM, half-warp gate split.
// 192 threads = 6 warps = 2 batches x 3 layers; one warp per (batch, layer).
// Lanes 0-15 (lo) own packed gate rows (u, u+32) = (i,g); lanes 16-31 (hi)
// own (u+16, u+48) = (f,o). Each lane's matvec is 16 fma2 (half of before).
// Gate products exchanged via 2 shfl_xor(16); c,h computed redundantly and
// bit-identically in both halves. Producer warp also computes layer l+1's
// input projection (16 fma2/lane) into pring.
// ---------------------------------------------------------------------------
__global__ __launch_bounds__(192, 1) void lstm_pipe(
    const float* __restrict__ Whh0,
    const float* __restrict__ Wih1, const float* __restrict__ Whh1,
    const float* __restrict__ bih1, const float* __restrict__ bhh1,
    const float* __restrict__ Wih2, const float* __restrict__ Whh2,
    const float* __restrict__ bih2, const float* __restrict__ bhh2,
    const int*   __restrict__ lengths)
{
    __shared__ __align__(16) ulonglong2 xring[2][XD][16];      // L0 gate inputs
    __shared__ __align__(16) ulonglong2 pring[2][PD][2][18];   // L1/L2 projections
    __shared__ __align__(16) float2     hring[3][2][2][20];    // own-h, duplicated

    const unsigned FULL = 0xffffffffu;
    int tid  = threadIdx.x;
    int wid  = tid >> 5;
    int lane = tid & 31;
    int lw   = wid % 3;                // layer index
    int sub  = wid / 3;                // batch element of the pair
    int half = lane >> 4;              // 0: (i,g) rows, 1: (f,o) rows
    int u    = lane & 15;
    int b    = blockIdx.x * 2 + sub;

    for (int i = tid; i < 3 * 2 * 2 * 20; i += 192)
        ((float2*)hring)[i] = make_float2(0.f, 0.f);

    // This lane's two gate rows (own half)
    int row0 = u + half * 16;          // i-row (lo) / f-row (hi)
    int row1 = u + 32 + half * 16;     // g-row (lo) / o-row (hi)

    ull hw[16], xw[16];
    ull pb = 0ull;                     // next layer's bias for the projection
    {
        const float* Wh = (lw == 0) ? Whh0 : (lw == 1) ? Whh1 : Whh2;
        const float* Wi = (lw == 0) ? Wih1 : (lw == 1) ? Wih2 : nullptr;
        const float* bi = (lw == 0) ? bih1 : (lw == 1) ? bih2 : nullptr;
        const float* bh = (lw == 0) ? bhh1 : (lw == 1) ? bhh2 : nullptr;
        #pragma unroll
        for (int k = 0; k < 16; k++) {
            hw[k] = pk2(Wh[row0 * 16 + k], Wh[row1 * 16 + k]);
            xw[k] = Wi ? pk2(Wi[row0 * 16 + k], Wi[row1 * 16 + k]) : 0ull;
        }
        if (bi) pb = pk2(bi[row0] + bh[row0], bi[row1] + bh[row1]);
    }

    int len = lengths[b];
    float* hout = g_h + (size_t)b * Tt * Hh;
    const float* xsrc = g_xg + (size_t)b * Tt * G4;
    uint32_t xdst0 = (uint32_t)__cvta_generic_to_shared(&xring[sub][0][u]);

    // L0 warps: prefill xg ring with steps 0..15 (lanes 0-15, 16B each)
    if (lw == 0 && half == 0) {
        #pragma unroll
        for (int s = 0; s < 2 * IV; s++) {
            cp_async16(xdst0 + s * 256, xsrc + (size_t)s * G4 + u * 4);
            cp_commit();
        }
    }

    float h = 0.f, c = 0.f, sm = 0.f, sq = 0.f;

    __syncthreads();

    for (int iv = 0; iv < NIV + 2; iv++) {
        int t0 = IV * (iv - lw);
        if (lw == 0) {
            // commit next 8 steps (16-step lead), clamped; lanes 0-15 only
            #pragma unroll
            for (int s = 0; s < IV; s++) {
                int st = iv * IV + 2 * IV + s;
                int stc = st < Tt ? st : Tt - 1;
                if (half == 0)
                    cp_async16(xdst0 + (st & (XD - 1)) * 256,
                               xsrc + (size_t)stc * G4 + u * 4);
                cp_commit();
            }
            cp_wait<2 * IV>();           // steps <= IV*iv+IV-1 resident
        }

        if (t0 + IV - 1 >= 0 && t0 < Tt) {
            #pragma unroll
            for (int s = 0; s < IV; s++) {
                int t = t0 + s;
                if (t < 0 || t >= Tt) continue;

                // this half's packed gate input (8B): (i,g) for lo, (f,o) for hi
                ull X = (lw == 0)
                    ? ((const ull*)&xring[sub][t & (XD - 1)][0])[2 * u + half]
                    : ((const ull*)&pring[lw - 1][t & (PD - 1)][sub][0])[2 * u + half];

                const ulonglong2* Hv =
                    (const ulonglong2*)&hring[lw][(t - 1) & 1][sub][0];
                // 16 fma2, 4-way split (chain depth 4)
                ull a0 = X, a1 = 0ull, a2 = 0ull, a3 = 0ull;
                #pragma unroll
                for (int j = 0; j < 4; j++) {
                    ulonglong2 H = Hv[j];
                    a0 = fma2(hw[4 * j],     H.x, a0);
                    a1 = fma2(hw[4 * j + 1], H.x, a1);
                    a2 = fma2(hw[4 * j + 2], H.y, a2);
                    a3 = fma2(hw[4 * j + 3], H.y, a3);
                }
                // NOTE: Hv[j] covers units 4j..4j+3 as two packed pairs; the
                // weight indexing must match: hw[k] multiplies (h_k, h_k).
                // Hv[j].x = (h_{4j},h_{4j}) pairs with hw[4j],   hw[4j+1]? No —
                // correct pairing below via re-read loop (kept simple & right):
                a0 = X; a1 = 0ull; a2 = 0ull; a3 = 0ull;
                #pragma unroll
                for (int j = 0; j < 4; j++) {
                    ulonglong2 H0 = Hv[2 * j];         // units 4j, 4j+1? see layout
                    ulonglong2 H1 = Hv[2 * j + 1];
                    a0 = fma2(hw[4 * j],     H0.x, a0);
                    a1 = fma2(hw[4 * j + 1], H0.y, a1);
                    a2 = fma2(hw[4 * j + 2], H1.x, a2);
                    a3 = fma2(hw[4 * j + 3], H1.y, a3);
                }
                float v0, v1;
                upk2(add2(add2(a0, a1), add2(a2, a3)), v0, v1);
                // lo: (gi, gg)   hi: (gf, go)
                float A = siga(v0);                       // sig_i / sig_f
                float arg = half ? 0.5f * v1 : v1;
                float tb  = tanha(arg);
                float Bv  = half ? fmaf(0.5f, tb, 0.5f) : tb;  // sig_o / tanh_g
                float zo  = A * Bv;                       // lo: z = sig_i*tanh_g
                float p = __shfl_xor_sync(FULL, half ? A : zo, 16); // lo<-sig_f, hi<-z
                float q = __shfl_xor_sync(FULL, Bv, 16);            // lo<-sig_o
                float sig_f = half ? A : p;
                float zz    = half ? p : zo;
                float sig_o = half ? Bv : q;
                c = fmaf(sig_f, c, zz);
                float tc = tanha(c);
                h = sig_o * tc;
                if (!half) hring[lw][t & 1][sub][u] = make_float2(h, h);
                __syncwarp();

                if (lw < 2) {
                    // projection for layer lw+1 (own half's packed rows)
                    const ulonglong2* Hn =
                        (const ulonglong2*)&hring[lw][t & 1][sub][0];
                    ull p0 = pb, p1 = 0ull, p2 = 0ull, p3 = 0ull;
                    #pragma unroll
                    for (int j = 0; j < 4; j++) {
                        ulonglong2 H0 = Hn[2 * j];
                        ulonglong2 H1 = Hn[2 * j + 1];
                        p0 = fma2(xw[4 * j],     H0.x, p0);
                        p1 = fma2(xw[4 * j + 1], H0.y, p1);
                        p2 = fma2(xw[4 * j + 2], H1.x, p2);
                        p3 = fma2(xw[4 * j + 3], H1.y, p3);
                    }
                    ull P = add2(add2(p0, p1), add2(p2, p3));
                    ((ull*)&pring[lw][t & (PD - 1)][sub][0])[2 * u + half] = P;
                } else if (!half) {
                    float hm = (t < len) ? h : 0.f;
                    hout[t * Hh + u] = hm;
                    sm += hm;  sq += hm * hm;
                }
            }
        }
        __syncthreads();
    }

    if (lw == 2 && half == 0) {
        g_psum[b * Hh + u] = sm;
        g_psq [b * Hh + u] = sq;
    }
}

// ---------------------------------------------------------------------------
// Kernel 3: reduce BN stats -> per-channel scale/shift
// ---------------------------------------------------------------------------
__global__ void stats_kernel(const float* __restrict__ gamma,
                             const float* __restrict__ beta) {
    int tid = threadIdx.x;
    if (tid < Hh) {
        float s = 0.f, q = 0.f;
        #pragma unroll 8
        for (int i = 0; i < Bsz; i++) {
            s += g_psum[i * Hh + tid];
            q += g_psq [i * Hh + tid];
        }
        const float inv = 1.f / (float)((size_t)Bsz * Tt);
        float mean = s * inv;
        float var  = q * inv - mean * mean;
        float sc   = gamma[tid] * rsqrtf(var + 1e-5f);
        g_scale[tid] = sc;
        g_shift[tid] = beta[tid] - mean * sc;
    }
}

// ---------------------------------------------------------------------------
// Kernel 4: out[bt, o] = c2[o] + sum_k h[bt,k] * (scale[k]*fc_w[o,k])
// ---------------------------------------------------------------------------
__global__ void finalize_kernel(const float* __restrict__ fcw,
                                const float* __restrict__ fcb,
                                float* __restrict__ out) {
    __shared__ float w2[64];
    __shared__ float c2[4];
    __shared__ float sh_shift[16];
    int tid = threadIdx.x;
    if (tid < 16) sh_shift[tid] = g_shift[tid];
    if (tid < 64) w2[tid] = g_scale[tid & 15] * fcw[tid];
    __syncthreads();
    if (tid < 4) {
        float acc = fcb[tid];
        #pragma unroll
        for (int k = 0; k < 16; k++) acc += sh_shift[k] * fcw[tid * 16 + k];
        c2[tid] = acc;
    }
    __syncthreads();

    size_t r = (size_t)blockIdx.x * blockDim.x + tid;   // bt index
    const float4* hp = (const float4*)(g_h + r * Hh);
    float4 v0 = hp[0], v1 = hp[1], v2 = hp[2], v3 = hp[3];
    float hh[16] = {v0.x, v0.y, v0.z, v0.w, v1.x, v1.y, v1.z, v1.w,
                    v2.x, v2.y, v2.z, v2.w, v3.x, v3.y, v3.z, v3.w};
    float o0 = c2[0], o1 = c2[1], o2 = c2[2], o3 = c2[3];
    #pragma unroll
    for (int k = 0; k < 16; k++) {
        float hv = hh[k];
        o0 += hv * w2[k];
        o1 += hv * w2[16 + k];
        o2 += hv * w2[32 + k];
        o3 += hv * w2[48 + k];
    }
    ((float4*)out)[r] = make_float4(o0, o1, o2, o3);
}

// ---------------------------------------------------------------------------
extern "C" void kernel_launch(void* const* d_in, const int* in_sizes, int n_in,
                              void* d_out, int out_size) {
    const float* x      = (const float*)d_in[0];
    const int*   lens   = (const int*)  d_in[1];
    const float* W_ih0  = (const float*)d_in[2];
    const float* W_hh0  = (const float*)d_in[3];
    const float* b_ih0  = (const float*)d_in[4];
    const float* b_hh0  = (const float*)d_in[5];
    const float* W_ih1  = (const float*)d_in[6];
    const float* W_hh1  = (const float*)d_in[7];
    const float* b_ih1  = (const float*)d_in[8];
    const float* b_hh1  = (const float*)d_in[9];
    const float* W_ih2  = (const float*)d_in[10];
    const float* W_hh2  = (const float*)d_in[11];
    const float* b_ih2  = (const float*)d_in[12];
    const float* b_hh2  = (const float*)d_in[13];
    const float* gamma  = (const float*)d_in[14];
    const float* beta   = (const float*)d_in[15];
    const float* fc_w   = (const float*)d_in[16];
    const float* fc_b   = (const float*)d_in[17];

    // Two no-op launches: shift ncu's capture slot (-s 5) onto lstm_pipe.
    nop_kernel<<<1, 32>>>();
    nop_kernel<<<1, 32>>>();
    gemm0_kernel<<<(Bsz * Tt) / GR, 512>>>(x, W_ih0, b_ih0, b_hh0);
    lstm_pipe<<<Bsz / 2, 192>>>(W_hh0, W_ih1, W_hh1, b_ih1, b_hh1,
                                W_ih2, W_hh2, b_ih2, b_hh2, lens);
    stats_kernel<<<1, 32>>>(gamma, beta);
    finalize_kernel<<<(Bsz * Tt) / 256, 256>>>(fc_w, fc_b, (float*)d_out);
}

// round 13
// speedup vs baseline: 1.1920x; 1.1920x over previous
#include <cuda_runtime.h>
#include <cstdint>

#define Bsz 256
#define Tt  2048
#define Dd  57
#define DP  60            // padded Dd (float4 friendly)
#define Hh  16
#define G4  64
#define GR  64            // rows per gemm0 block
#define IV  8             // steps per interval
#define NIV (Tt / IV)     // 256 intervals
#define XD  16            // xg ring depth (8-step lead; write t+8 vs read t, distinct mod 16)
#define PD  16            // projection ring depth
#define HD  16            // h ring depth (2 intervals)

typedef unsigned long long ull;

// Scratch (device-global: no allocation allowed in kernel_launch)
// g_xg layout per (b,t): 16 chunks of 16B; chunk u = (row u, row u+32,
// row u+16, row u+48) = (i,g,f,o) of unit u, biases included.
__device__ float g_xg[(size_t)Bsz * Tt * G4];
__device__ float g_h [(size_t)Bsz * Tt * Hh];   // masked layer-2 hidden states
__device__ float g_psum[Bsz * Hh];              // per-batch partial BN sums
__device__ float g_psq [Bsz * Hh];
__device__ float g_scale[Hh], g_shift[Hh];

// HW tanh (MUFU.TANH)
__device__ __forceinline__ float tanha(float x) {
    float y; asm("tanh.approx.f32 %0, %1;" : "=f"(y) : "f"(x)); return y;
}
__device__ __forceinline__ float siga(float x) {
    return fmaf(0.5f, tanha(0.5f * x), 0.5f);
}

// --- packed f32x2 helpers ---
__device__ __forceinline__ ull pk2(float a, float b) {
    ull r; asm("mov.b64 %0, {%1, %2};" : "=l"(r) : "f"(a), "f"(b)); return r;
}
__device__ __forceinline__ void upk2(ull v, float& a, float& b) {
    asm("mov.b64 {%0, %1}, %2;" : "=f"(a), "=f"(b) : "l"(v));
}
__device__ __forceinline__ ull fma2(ull a, ull b, ull c) {
    ull d; asm("fma.rn.f32x2 %0, %1, %2, %3;" : "=l"(d) : "l"(a), "l"(b), "l"(c));
    return d;
}
__device__ __forceinline__ ull add2(ull a, ull b) {
    ull d; asm("add.rn.f32x2 %0, %1, %2;" : "=l"(d) : "l"(a), "l"(b));
    return d;
}

__device__ __forceinline__ void cp_async16(uint32_t smem_addr, const void* gptr) {
    asm volatile("cp.async.cg.shared.global [%0], [%1], 16;"
                 :: "r"(smem_addr), "l"(gptr) : "memory");
}
__device__ __forceinline__ void cp_commit() {
    asm volatile("cp.async.commit_group;" ::: "memory");
}
template <int N>
__device__ __forceinline__ void cp_wait() {
    asm volatile("cp.async.wait_group %0;" :: "n"(N) : "memory");
}

// No-op kernel: shifts ncu's capture slot (-s 5) onto lstm_pipe.
__global__ void nop_kernel() {}

// ---------------------------------------------------------------------------
// Kernel 1: xg0 = x @ W_ih0^T + b.  64 rows/block, interleaved output.
// ---------------------------------------------------------------------------
__global__ __launch_bounds__(512) void gemm0_kernel(
    const float* __restrict__ x,
    const float* __restrict__ W,
    const float* __restrict__ bi,
    const float* __restrict__ bh) {
    __shared__ float Ws[G4 * DP];
    __shared__ float bs[G4];
    __shared__ float xs[GR * DP];
    int tid = threadIdx.x;

    for (int i = tid; i < G4 * DP; i += 512) Ws[i] = 0.f;
    for (int i = tid; i < GR * DP; i += 512) xs[i] = 0.f;
    __syncthreads();
    for (int i = tid; i < G4 * Dd; i += 512)
        Ws[(i / Dd) * DP + (i % Dd)] = W[i];
    if (tid < G4) bs[tid] = bi[tid] + bh[tid];
    size_t r0 = (size_t)blockIdx.x * GR;
    for (int i = tid; i < GR * Dd; i += 512)
        xs[(i / Dd) * DP + (i % Dd)] = x[r0 * Dd + i];
    __syncthreads();

    int g  = tid & 63;
    int y0 = tid >> 6;            // rows y0, y0+8, ..., y0+56
    float acc[8];
    #pragma unroll
    for (int m = 0; m < 8; m++) acc[m] = bs[g];

    const float4* Ws4 = (const float4*)Ws;
    const float4* xs4 = (const float4*)xs;
    #pragma unroll
    for (int d4 = 0; d4 < DP / 4; d4++) {
        float4 wv = Ws4[g * (DP / 4) + d4];
        #pragma unroll
        for (int m = 0; m < 8; m++) {
            float4 xv = xs4[(y0 + 8 * m) * (DP / 4) + d4];
            acc[m] += xv.x * wv.x + xv.y * wv.y + xv.z * wv.z + xv.w * wv.w;
        }
    }

    int pos = (g & 15) * 4 + ((g >> 4) & 1) * 2 + (g >> 5);
    #pragma unroll
    for (int m = 0; m < 8; m++)
        g_xg[(r0 + y0 + 8 * m) * G4 + pos] = acc[m];
}

// ---------------------------------------------------------------------------
// Kernel 2: warp-specialized layer-pipelined LSTM. 224 threads = 7 warps:
//   wid 0/1/2 : recurrence warps for layers 0/1/2 (2 subs via lane>>4;
//               lane u owns all 4 gates of unit u; 32 fma2/step, no proj)
//   wid 3..6  : projection warps (trans=(wid-3)>>1, sub=(wid-3)&1); 32-lane
//               half-split, 16 fma2/step, write pring for the next layer.
// Interval skews: L0=0, P0=1, L1=2, P1=3, L2=4. Barrier once per interval.
// ---------------------------------------------------------------------------
__global__ __launch_bounds__(224, 1) void lstm_pipe(
    const float* __restrict__ Whh0,
    const float* __restrict__ Wih1, const float* __restrict__ Whh1,
    const float* __restrict__ bih1, const float* __restrict__ bhh1,
    const float* __restrict__ Wih2, const float* __restrict__ Whh2,
    const float* __restrict__ bih2, const float* __restrict__ bhh2,
    const int*   __restrict__ lengths)
{
    __shared__ __align__(16) ulonglong2 xring[2][XD][16];      // L0 gate inputs
    __shared__ __align__(16) ulonglong2 pring[2][PD][2][18];   // L1/L2 projections
    __shared__ __align__(16) float2     hring[3][HD][2][20];   // h, duplicated

    int tid  = threadIdx.x;
    int wid  = tid >> 5;
    int lane = tid & 31;
    bool isRec = wid < 3;

    for (int i = tid; i < 3 * HD * 2 * 20; i += 224)
        ((float2*)hring)[i] = make_float2(0.f, 0.f);

    if (isRec) {
        // ================= recurrence warp (layer lw) =================
        int lw  = wid;
        int sub = lane >> 4;
        int u   = lane & 15;
        int b   = blockIdx.x * 2 + sub;
        int d   = 2 * lw;              // interval skew

        ull hig[16], hfo[16];
        {
            const float* Wh = (lw == 0) ? Whh0 : (lw == 1) ? Whh1 : Whh2;
            #pragma unroll
            for (int k = 0; k < 16; k++) {
                hig[k] = pk2(Wh[u * 16 + k],        Wh[(u + 32) * 16 + k]);
                hfo[k] = pk2(Wh[(u + 16) * 16 + k], Wh[(u + 48) * 16 + k]);
            }
        }

        int len = lengths[b];
        float* hout = g_h + (size_t)b * Tt * Hh;
        const float* xsrc = g_xg + (size_t)b * Tt * G4;
        uint32_t xdst0 = (uint32_t)__cvta_generic_to_shared(&xring[sub][0][u]);

        // L0: prefill xg ring with steps 0..7 (8 groups; 8-step lead)
        if (lw == 0) {
            #pragma unroll
            for (int s = 0; s < IV; s++) {
                cp_async16(xdst0 + s * 256, xsrc + (size_t)s * G4 + u * 4);
                cp_commit();
            }
        }

        float h = 0.f, c = 0.f, sm = 0.f, sq = 0.f;
        __syncthreads();

        for (int iv = 0; iv < NIV + 4; iv++) {
            int t0 = IV * (iv - d);
            if (lw == 0) {
                #pragma unroll
                for (int s = 0; s < IV; s++) {
                    int st = iv * IV + IV + s;
                    int stc = st < Tt ? st : Tt - 1;
                    cp_async16(xdst0 + (st & (XD - 1)) * 256,
                               xsrc + (size_t)stc * G4 + u * 4);
                    cp_commit();
                }
                cp_wait<IV>();          // steps <= IV*iv+IV-1 resident
            }

            if (t0 + IV - 1 >= 0 && t0 < Tt) {
                #pragma unroll
                for (int s = 0; s < IV; s++) {
                    int t = t0 + s;
                    if (t < 0 || t >= Tt) continue;

                    ulonglong2 X = (lw == 0)
                        ? xring[sub][t & (XD - 1)][u]
                        : pring[lw - 1][t & (PD - 1)][sub][u];

                    const ulonglong2* Hv =
                        (const ulonglong2*)&hring[lw][(t - 1) & (HD - 1)][sub][0];
                    ull a0 = X.x, a1 = 0ull, a2 = 0ull, a3 = 0ull;
                    ull f0 = X.y, f1 = 0ull, f2 = 0ull, f3 = 0ull;
                    #pragma unroll
                    for (int j = 0; j < 4; j++) {
                        ulonglong2 H0 = Hv[2 * j];
                        ulonglong2 H1 = Hv[2 * j + 1];
                        a0 = fma2(hig[4 * j],     H0.x, a0);
                        a1 = fma2(hig[4 * j + 1], H0.y, a1);
                        a2 = fma2(hig[4 * j + 2], H1.x, a2);
                        a3 = fma2(hig[4 * j + 3], H1.y, a3);
                        f0 = fma2(hfo[4 * j],     H0.x, f0);
                        f1 = fma2(hfo[4 * j + 1], H0.y, f1);
                        f2 = fma2(hfo[4 * j + 2], H1.x, f2);
                        f3 = fma2(hfo[4 * j + 3], H1.y, f3);
                    }
                    float gi, gg, gf, go;
                    upk2(add2(add2(a0, a1), add2(a2, a3)), gi, gg);
                    upk2(add2(add2(f0, f1), add2(f2, f3)), gf, go);
                    c = siga(gf) * c + siga(gi) * tanha(gg);
                    h = siga(go) * tanha(c);
                    hring[lw][t & (HD - 1)][sub][u] = make_float2(h, h);
                    __syncwarp();

                    if (lw == 2) {
                        float hm = (t < len) ? h : 0.f;
                        hout[t * Hh + u] = hm;
                        sm += hm;  sq += hm * hm;
                    }
                }
            }
            __syncthreads();
        }

        if (lw == 2) {
            g_psum[b * Hh + u] = sm;
            g_psq [b * Hh + u] = sq;
        }
    } else {
        // ================= projection warp =================
        int trans = (wid - 3) >> 1;    // 0: L0->L1, 1: L1->L2
        int psub  = (wid - 3) & 1;
        int half  = lane >> 4;
        int u     = lane & 15;
        int d     = 1 + 2 * trans;     // interval skew
        int row0  = u + half * 16;     // i-row (lo) / f-row (hi)
        int row1  = u + 32 + half * 16;// g-row (lo) / o-row (hi)

        ull xw[16];
        ull pb;
        {
            const float* Wi = (trans == 0) ? Wih1 : Wih2;
            const float* bi = (trans == 0) ? bih1 : bih2;
            const float* bh = (trans == 0) ? bhh1 : bhh2;
            #pragma unroll
            for (int k = 0; k < 16; k++)
                xw[k] = pk2(Wi[row0 * 16 + k], Wi[row1 * 16 + k]);
            pb = pk2(bi[row0] + bh[row0], bi[row1] + bh[row1]);
        }

        __syncthreads();

        for (int iv = 0; iv < NIV + 4; iv++) {
            int t0 = IV * (iv - d);
            if (t0 + IV - 1 >= 0 && t0 < Tt) {
                #pragma unroll
                for (int s = 0; s < IV; s++) {
                    int t = t0 + s;
                    if (t < 0 || t >= Tt) continue;
                    const ulonglong2* Hn =
                        (const ulonglong2*)&hring[trans][t & (HD - 1)][psub][0];
                    ull p0 = pb, p1 = 0ull, p2 = 0ull, p3 = 0ull;
                    #pragma unroll
                    for (int j = 0; j < 4; j++) {
                        ulonglong2 H0 = Hn[2 * j];
                        ulonglong2 H1 = Hn[2 * j + 1];
                        p0 = fma2(xw[4 * j],     H0.x, p0);
                        p1 = fma2(xw[4 * j + 1], H0.y, p1);
                        p2 = fma2(xw[4 * j + 2], H1.x, p2);
                        p3 = fma2(xw[4 * j + 3], H1.y, p3);
                    }
                    ull P = add2(add2(p0, p1), add2(p2, p3));
                    ((ull*)&pring[trans][t & (PD - 1)][psub][0])[2 * u + half] = P;
                }
            }
            __syncthreads();
        }
    }
}

// ---------------------------------------------------------------------------
// Kernel 3: reduce BN stats -> per-channel scale/shift
// ---------------------------------------------------------------------------
__global__ void stats_kernel(const float* __restrict__ gamma,
                             const float* __restrict__ beta) {
    int tid = threadIdx.x;
    if (tid < Hh) {
        float s = 0.f, q = 0.f;
        #pragma unroll 8
        for (int i = 0; i < Bsz; i++) {
            s += g_psum[i * Hh + tid];
            q += g_psq [i * Hh + tid];
        }
        const float inv = 1.f / (float)((size_t)Bsz * Tt);
        float mean = s * inv;
        float var  = q * inv - mean * mean;
        float sc   = gamma[tid] * rsqrtf(var + 1e-5f);
        g_scale[tid] = sc;
        g_shift[tid] = beta[tid] - mean * sc;
    }
}

// ---------------------------------------------------------------------------
// Kernel 4: out[bt, o] = c2[o] + sum_k h[bt,k] * (scale[k]*fc_w[o,k])
// ---------------------------------------------------------------------------
__global__ void finalize_kernel(const float* __restrict__ fcw,
                                const float* __restrict__ fcb,
                                float* __restrict__ out) {
    __shared__ float w2[64];
    __shared__ float c2[4];
    __shared__ float sh_shift[16];
    int tid = threadIdx.x;
    if (tid < 16) sh_shift[tid] = g_shift[tid];
    if (tid < 64) w2[tid] = g_scale[tid & 15] * fcw[tid];
    __syncthreads();
    if (tid < 4) {
        float acc = fcb[tid];
        #pragma unroll
        for (int k = 0; k < 16; k++) acc += sh_shift[k] * fcw[tid * 16 + k];
        c2[tid] = acc;
    }
    __syncthreads();

    size_t r = (size_t)blockIdx.x * blockDim.x + tid;   // bt index
    const float4* hp = (const float4*)(g_h + r * Hh);
    float4 v0 = hp[0], v1 = hp[1], v2 = hp[2], v3 = hp[3];
    float hh[16] = {v0.x, v0.y, v0.z, v0.w, v1.x, v1.y, v1.z, v1.w,
                    v2.x, v2.y, v2.z, v2.w, v3.x, v3.y, v3.z, v3.w};
    float o0 = c2[0], o1 = c2[1], o2 = c2[2], o3 = c2[3];
    #pragma unroll
    for (int k = 0; k < 16; k++) {
        float hv = hh[k];
        o0 += hv * w2[k];
        o1 += hv * w2[16 + k];
        o2 += hv * w2[32 + k];
        o3 += hv * w2[48 + k];
    }
    ((float4*)out)[r] = make_float4(o0, o1, o2, o3);
}

// ---------------------------------------------------------------------------
extern "C" void kernel_launch(void* const* d_in, const int* in_sizes, int n_in,
                              void* d_out, int out_size) {
    const float* x      = (const float*)d_in[0];
    const int*   lens   = (const int*)  d_in[1];
    const float* W_ih0  = (const float*)d_in[2];
    const float* W_hh0  = (const float*)d_in[3];
    const float* b_ih0  = (const float*)d_in[4];
    const float* b_hh0  = (const float*)d_in[5];
    const float* W_ih1  = (const float*)d_in[6];
    const float* W_hh1  = (const float*)d_in[7];
    const float* b_ih1  = (const float*)d_in[8];
    const float* b_hh1  = (const float*)d_in[9];
    const float* W_ih2  = (const float*)d_in[10];
    const float* W_hh2  = (const float*)d_in[11];
    const float* b_ih2  = (const float*)d_in[12];
    const float* b_hh2  = (const float*)d_in[13];
    const float* gamma  = (const float*)d_in[14];
    const float* beta   = (const float*)d_in[15];
    const float* fc_w   = (const float*)d_in[16];
    const float* fc_b   = (const float*)d_in[17];

    // Two no-op launches: shift ncu's capture slot (-s 5) onto lstm_pipe.
    nop_kernel<<<1, 32>>>();
    nop_kernel<<<1, 32>>>();
    gemm0_kernel<<<(Bsz * Tt) / GR, 512>>>(x, W_ih0, b_ih0, b_hh0);
    lstm_pipe<<<Bsz / 2, 224>>>(W_hh0, W_ih1, W_hh1, b_ih1, b_hh1,
                                W_ih2, W_hh2, b_ih2, b_hh2, lens);
    stats_kernel<<<1, 32>>>(gamma, beta);
    finalize_kernel<<<(Bsz * Tt) / 256, 256>>>(fc_w, fc_b, (float*)d_out);
}